// round 14
// baseline (speedup 1.0000x reference)
#include <cuda_runtime.h>
#include <cuda_bf16.h>
#include <cstdint>

#define DM 1024
#define NH 16
#define DH 64
#define BB 2
#define TT 2048
#define MT (BB*TT)    // 4096 rows total
#define CH 128        // chunk size
#define NC (TT/CH)    // 16 chunks

// ---- scratch (no allocations allowed) ----
__device__ float g_q[MT*DM];
__device__ float g_k[MT*DM];
__device__ float g_v[MT*DM];
__device__ float g_y[MT*DM];
__device__ float g_part[BB*NH*NC*2];      // per-(bh,chunk) GN partials
__device__ float g_P2[BB*NH*NC*2*DH*DH];  // split-K partial states (2 halves)
__device__ float g_S[BB*NH*NC*DH*DH];
__device__ __nv_bfloat16 g_ah[MT*DM];     // activation hi
__device__ __nv_bfloat16 g_al[MT*DM];     // activation lo
__device__ __nv_bfloat16 g_wh[4*DM*DM];   // weight hi (q,k,v,o)
__device__ __nv_bfloat16 g_wl[4*DM*DM];   // weight lo

// ============================================================
// helpers
// ============================================================
__device__ __forceinline__ uint32_t smem_u32(const void* p) {
    uint32_t a;
    asm("{ .reg .u64 t; cvta.to.shared.u64 t, %1; cvt.u32.u64 %0, t; }" : "=r"(a) : "l"(p));
    return a;
}

#define CP16(smem_addr, gptr) \
    asm volatile("cp.async.cg.shared.global [%0], [%1], 16;" :: "r"(smem_addr), "l"(gptr))

__device__ __forceinline__ void ldmx4(uint32_t* r, uint32_t addr) {
    asm volatile("ldmatrix.sync.aligned.m8n8.x4.shared.b16 {%0,%1,%2,%3}, [%4];"
        : "=r"(r[0]), "=r"(r[1]), "=r"(r[2]), "=r"(r[3]) : "r"(addr));
}

__device__ __forceinline__ void mma16816(float* d, const uint32_t* a, uint32_t b0, uint32_t b1) {
    asm volatile("mma.sync.aligned.m16n8k16.row.col.f32.bf16.bf16.f32 "
        "{%0,%1,%2,%3}, {%4,%5,%6,%7}, {%8,%9}, {%0,%1,%2,%3};"
        : "+f"(d[0]), "+f"(d[1]), "+f"(d[2]), "+f"(d[3])
        : "r"(a[0]), "r"(a[1]), "r"(a[2]), "r"(a[3]), "r"(b0), "r"(b1));
}

__device__ __forceinline__ void split1(float x, __nv_bfloat16& h, __nv_bfloat16& l) {
    h = __float2bfloat16(x);
    l = __float2bfloat16(x - __bfloat162float(h));
}

// ============================================================
// merged split: one launch covers x (4 quarters) + 4 weights.
// ============================================================
__global__ void split_all(const float* __restrict__ x,
                          const float* __restrict__ Wq, const float* __restrict__ Wk,
                          const float* __restrict__ Wv, const float* __restrict__ Wo,
                          __nv_bfloat16* __restrict__ ah, __nv_bfloat16* __restrict__ al,
                          __nv_bfloat16* __restrict__ wh, __nv_bfloat16* __restrict__ wl)
{
    const int yy = blockIdx.y;
    const size_t i = (size_t)blockIdx.x * blockDim.x + threadIdx.x;
    const size_t e = i * 4;
    const float* src;
    __nv_bfloat16 *hp, *lp;
    if (yy < 4) {
        src = x  + (size_t)yy * (MT*DM/4) + e;
        hp  = ah + (size_t)yy * (MT*DM/4) + e;
        lp  = al + (size_t)yy * (MT*DM/4) + e;
    } else {
        const float* ws[4] = {Wq, Wk, Wv, Wo};
        src = ws[yy-4] + e;
        hp  = wh + (size_t)(yy-4) * DM*DM + e;
        lp  = wl + (size_t)(yy-4) * DM*DM + e;
    }
    float4 xx = *(const float4*)src;
    __nv_bfloat16 h0, h1, h2, h3, l0, l1, l2, l3;
    split1(xx.x, h0, l0); split1(xx.y, h1, l1);
    split1(xx.z, h2, l2); split1(xx.w, h3, l3);
    ((__nv_bfloat162*)hp)[0] = __nv_bfloat162(h0, h1);
    ((__nv_bfloat162*)hp)[1] = __nv_bfloat162(h2, h3);
    ((__nv_bfloat162*)lp)[0] = __nv_bfloat162(l0, l1);
    ((__nv_bfloat162*)lp)[1] = __nv_bfloat162(l2, l3);
}

// ============================================================
// HMMA bf16 GEMM with Ootomo split; batched over blockIdx.z.
// ============================================================
#define GSM_BYTES (2*4*128*40*2)   // 81920

__global__ __launch_bounds__(256, 2)
void gemm_mma(const __nv_bfloat16* __restrict__ Ah, const __nv_bfloat16* __restrict__ Al,
              const __nv_bfloat16* __restrict__ Wh, const __nv_bfloat16* __restrict__ Wl,
              float* __restrict__ C0, float* __restrict__ C1, float* __restrict__ C2,
              int M, int N, int K, int wbase)
{
    extern __shared__ __nv_bfloat16 smh[];
    const uint32_t sbase = smem_u32(smh);
    const int tid = threadIdx.x;
    const int lane = tid & 31;
    const int w = tid >> 5;
    const int wr = w >> 2;
    const int wc = w & 3;
    const int m0 = blockIdx.y * 128;
    const int n0 = blockIdx.x * 128;
    const int z = blockIdx.z;

    float* C = (z == 0) ? C0 : (z == 1) ? C1 : C2;
    const size_t woff = (size_t)(wbase + z) * DM * DM;
    const __nv_bfloat16* Bh = Wh + woff;
    const __nv_bfloat16* Bl = Wl + woff;

    const int lrow = tid >> 2;
    const int lc16 = tid & 3;

    const __nv_bfloat16* gsrc[4] = {Ah, Al, Bh, Bl};

    float acc[4][4][4];
    #pragma unroll
    for (int m = 0; m < 4; m++)
        #pragma unroll
        for (int n = 0; n < 4; n++)
            #pragma unroll
            for (int e = 0; e < 4; e++) acc[m][n][e] = 0.f;

    const int NCH = K >> 5;

    auto load_stage = [&](int s, int k0) {
        uint32_t sb = sbase + (uint32_t)s * 20480u * 2u;
        #pragma unroll
        for (int arr = 0; arr < 4; arr++) {
            const __nv_bfloat16* g = gsrc[arr];
            int base_row = (arr < 2) ? m0 : n0;
            #pragma unroll
            for (int half = 0; half < 2; half++) {
                int row = lrow + half * 64;
                uint32_t so = sb + (uint32_t)(arr * 5120 + row * 40 + lc16 * 8) * 2u;
                const __nv_bfloat16* gp = g + (size_t)(base_row + row) * K + k0 + lc16 * 8;
                CP16(so, gp);
            }
        }
    };

    load_stage(0, 0);
    asm volatile("cp.async.commit_group;" ::: "memory");

    for (int c = 0; c < NCH; ++c) {
        const int s = c & 1;
        if (c + 1 < NCH) {
            load_stage(s ^ 1, (c + 1) << 5);
            asm volatile("cp.async.commit_group;" ::: "memory");
            asm volatile("cp.async.wait_group 1;" ::: "memory");
        } else {
            asm volatile("cp.async.wait_group 0;" ::: "memory");
        }
        __syncthreads();

        const uint32_t sb = sbase + (uint32_t)s * 20480u * 2u;
        const uint32_t sA  = sb;
        const uint32_t sAl = sb + 5120u * 2u;
        const uint32_t sB  = sb + 10240u * 2u;
        const uint32_t sBl = sb + 15360u * 2u;

        #pragma unroll
        for (int kk = 0; kk < 2; ++kk) {
            const int kb = kk * 16;
            uint32_t ah4[4][4], al4[4][4];
            const uint32_t arow = (uint32_t)(wr * 64 + (lane & 15));
            const uint32_t acol = (uint32_t)(kb + (lane >> 4) * 8);
            #pragma unroll
            for (int m = 0; m < 4; m++) {
                uint32_t off = ((arow + m * 16) * 40u + acol) * 2u;
                ldmx4(ah4[m], sA  + off);
                ldmx4(al4[m], sAl + off);
            }
            uint32_t bh4[2][4], bl4[2][4];
            const uint32_t brow = (uint32_t)(wc * 32 + (lane & 7) + ((lane >> 4) << 3));
            const uint32_t bcol = (uint32_t)(kb + ((lane >> 3) & 1) * 8);
            #pragma unroll
            for (int p = 0; p < 2; p++) {
                uint32_t off = ((brow + p * 16) * 40u + bcol) * 2u;
                ldmx4(bh4[p], sB  + off);
                ldmx4(bl4[p], sBl + off);
            }
            #pragma unroll
            for (int m = 0; m < 4; m++) {
                #pragma unroll
                for (int n = 0; n < 4; n++) {
                    uint32_t b0 = bh4[n >> 1][(n & 1) * 2];
                    uint32_t b1 = bh4[n >> 1][(n & 1) * 2 + 1];
                    uint32_t c0 = bl4[n >> 1][(n & 1) * 2];
                    uint32_t c1 = bl4[n >> 1][(n & 1) * 2 + 1];
                    mma16816(acc[m][n], ah4[m], b0, b1);
                    mma16816(acc[m][n], ah4[m], c0, c1);
                    mma16816(acc[m][n], al4[m], b0, b1);
                }
            }
        }
        __syncthreads();
    }

    const int r0 = m0 + wr * 64 + (lane >> 2);
    const int cc = n0 + wc * 32 + (lane & 3) * 2;
    #pragma unroll
    for (int m = 0; m < 4; m++) {
        #pragma unroll
        for (int n = 0; n < 4; n++) {
            float* p0 = C + (size_t)(r0 + m * 16) * N + cc + n * 8;
            float* p1 = C + (size_t)(r0 + m * 16 + 8) * N + cc + n * 8;
            *(float2*)p0 = make_float2(acc[m][n][0], acc[m][n][1]);
            *(float2*)p1 = make_float2(acc[m][n][2], acc[m][n][3]);
        }
    }
}

// ============================================================
// chunk_state split-K: grid (NC, BH, 2); each block does 64 j-rows
// ============================================================
__global__ __launch_bounds__(256)
void chunk_state(const float* __restrict__ kmat, const float* __restrict__ vmat,
                 float* __restrict__ P2)
{
    __shared__ float Ks[64][68];
    __shared__ float Vs[64][68];
    const int ch = blockIdx.x;
    const int bh = blockIdx.y;
    const int z  = blockIdx.z;
    const int b = bh >> 4, h = bh & 15;
    const float lg = log2f(1.f - exp2f(-5.f - (float)h));
    const int tid = threadIdx.x;
    const int j0 = ch * CH + z * 64;

    const float* kbase = kmat + ((size_t)(b*TT + j0))*DM + h*DH;
    const float* vbase = vmat + ((size_t)(b*TT + j0))*DM + h*DH;
    for (int s = tid; s < 64*16; s += 256) {
        int row = s >> 4, c4 = (s & 15) << 2;
        float sc = exp2f(lg * (float)(CH - z*64 - row));
        float4 kk = *(const float4*)(kbase + (size_t)row*DM + c4);
        Ks[row][c4+0] = kk.x*sc; Ks[row][c4+1] = kk.y*sc;
        Ks[row][c4+2] = kk.z*sc; Ks[row][c4+3] = kk.w*sc;
        float4 vv = *(const float4*)(vbase + (size_t)row*DM + c4);
        *(float4*)&Vs[row][c4] = vv;
    }
    __syncthreads();

    const int tr = tid >> 4, tc = tid & 15;
    float acc[4][4];
    #pragma unroll
    for (int i = 0; i < 4; i++)
        #pragma unroll
        for (int j = 0; j < 4; j++) acc[i][j] = 0.f;

    #pragma unroll 4
    for (int j = 0; j < 64; j++) {
        float ar[4], br[4];
        *(float4*)&ar[0] = *(const float4*)&Ks[j][tr*4];
        *(float4*)&br[0] = *(const float4*)&Vs[j][tc*4];
        #pragma unroll
        for (int i = 0; i < 4; i++)
            #pragma unroll
            for (int jj = 0; jj < 4; jj++)
                acc[i][jj] += ar[i] * br[jj];
    }

    float* pbase = P2 + ((size_t)((bh*NC + ch)*2 + z))*DH*DH;
    #pragma unroll
    for (int i = 0; i < 4; i++)
        *(float4*)(pbase + (tr*4 + i)*DH + tc*4) =
            make_float4(acc[i][0], acc[i][1], acc[i][2], acc[i][3]);
}

// ============================================================
// state_scan: parallel over elements.
// ============================================================
__global__ __launch_bounds__(256)
void state_scan(const float* __restrict__ P2, float* __restrict__ S)
{
    const int bh = blockIdx.y;
    const int e = blockIdx.x * 256 + threadIdx.x;   // 0..4095
    const int h = bh & 15;
    const float lg = log2f(1.f - exp2f(-5.f - (float)h));
    const float gC = exp2f(lg * (float)CH);

    float s = 0.f;
    #pragma unroll
    for (int n = 0; n < NC; n++) {
        const size_t sb = ((size_t)(bh*NC + n))*DH*DH;
        const size_t pb = ((size_t)(bh*NC + n))*2*DH*DH;
        S[sb + e] = s * 0.125f;
        float p0 = P2[pb + e];
        float p1 = P2[pb + DH*DH + e];
        s = gC * s + p0 + p1;
    }
}

// ============================================================
// retention_chunk (R11 fp32 version) + fused GN partial reduce
// ============================================================
#define RET_SMEM_FLOATS (64*132 + 64*68 + 64*68 + 128*68)

__global__ __launch_bounds__(256)
void retention_chunk(const float* __restrict__ q, const float* __restrict__ kmat,
                     const float* __restrict__ vmat, const float* __restrict__ Sg,
                     float* __restrict__ y, float* __restrict__ part)
{
    extern __shared__ float smf[];
    float (*QT)[132] = (float (*)[132])smf;
    float (*KT)[68]  = (float (*)[68])(smf + 64*132);
    float (*Vs)[68]  = (float (*)[68])(smf + 64*132 + 64*68);
    float (*Ss)[68]  = (float (*)[68])(smf + 64*132 + 2*64*68);

    const int it = blockIdx.x;
    const int bh = blockIdx.y;
    const int b = bh >> 4, h = bh & 15;
    const int i0 = it * CH;
    const float lg = log2f(1.f - exp2f(-5.f - (float)h));
    const int tid = threadIdx.x;
    const int tr = tid >> 4;
    const int tc = tid & 15;

    const float* qbase = q + ((size_t)(b*TT + i0))*DM + h*DH;
    for (int s = tid; s < CH*16; s += 256) {
        int row = s >> 4, c4 = (s & 15) << 2;
        float4 a = *(const float4*)(qbase + (size_t)row*DM + c4);
        float sc = exp2f(lg * (float)row);
        QT[c4+0][row] = a.x*sc; QT[c4+1][row] = a.y*sc;
        QT[c4+2][row] = a.z*sc; QT[c4+3][row] = a.w*sc;
    }
    const float* sbase = Sg + ((size_t)(bh*NC + it))*DH*DH;
    for (int s = tid; s < 64*16; s += 256) {
        int row = s >> 4, c4 = (s & 15) << 2;
        *(float4*)&KT[row][c4] = *(const float4*)(sbase + row*DH + c4);
    }
    __syncthreads();

    float accy[8][4];
    #pragma unroll
    for (int i = 0; i < 8; i++)
        #pragma unroll
        for (int j = 0; j < 4; j++) accy[i][j] = 0.f;

    #pragma unroll 8
    for (int a = 0; a < DH; a++) {
        float ar[8], br[4];
        *(float4*)&ar[0] = *(const float4*)&QT[a][tr*8];
        *(float4*)&ar[4] = *(const float4*)&QT[a][tr*8+4];
        *(float4*)&br[0] = *(const float4*)&KT[a][tc*4];
        #pragma unroll
        for (int i = 0; i < 8; i++)
            #pragma unroll
            for (int j = 0; j < 4; j++)
                accy[i][j] += ar[i] * br[j];
    }

    #pragma unroll
    for (int jt = 0; jt < 2; jt++) {
        const int j0 = i0 + (jt << 6);
        const int diffbase = -(jt << 6);
        const float* kbase = kmat + ((size_t)(b*TT + j0))*DM + h*DH;
        const float* vbase = vmat + ((size_t)(b*TT + j0))*DM + h*DH;
        __syncthreads();
        for (int s = tid; s < 64*16; s += 256) {
            int row = s >> 4, c4 = (s & 15) << 2;
            float sc = exp2f(-lg * (float)row);
            float4 kk = *(const float4*)(kbase + (size_t)row*DM + c4);
            KT[c4+0][row] = kk.x*sc; KT[c4+1][row] = kk.y*sc;
            KT[c4+2][row] = kk.z*sc; KT[c4+3][row] = kk.w*sc;
            float4 vv = *(const float4*)(vbase + (size_t)row*DM + c4);
            *(float4*)&Vs[row][c4] = vv;
        }
        __syncthreads();

        float acc1[8][4];
        #pragma unroll
        for (int i = 0; i < 8; i++)
            #pragma unroll
            for (int j = 0; j < 4; j++) acc1[i][j] = 0.f;
        #pragma unroll 8
        for (int c = 0; c < DH; c++) {
            float ar[8], br[4];
            *(float4*)&ar[0] = *(const float4*)&QT[c][tr*8];
            *(float4*)&ar[4] = *(const float4*)&QT[c][tr*8+4];
            *(float4*)&br[0] = *(const float4*)&KT[c][tc*4];
            #pragma unroll
            for (int i = 0; i < 8; i++)
                #pragma unroll
                for (int j = 0; j < 4; j++)
                    acc1[i][j] += ar[i] * br[j];
        }

        const float base = exp2f(lg * (float)diffbase) * 0.125f;
        #pragma unroll
        for (int i = 0; i < 8; i++) {
            const int ir = tr*8 + i;
            float o0 = acc1[i][0]*base, o1 = acc1[i][1]*base;
            float o2 = acc1[i][2]*base, o3 = acc1[i][3]*base;
            int d0 = diffbase + ir - (tc*4);
            if (d0     < 0) o0 = 0.f;
            if (d0 - 1 < 0) o1 = 0.f;
            if (d0 - 2 < 0) o2 = 0.f;
            if (d0 - 3 < 0) o3 = 0.f;
            *(float4*)&Ss[ir][tc*4] = make_float4(o0, o1, o2, o3);
        }
        __syncthreads();

        #pragma unroll 8
        for (int jr = 0; jr < 64; jr++) {
            float br[4];
            *(float4*)&br[0] = *(const float4*)&Vs[jr][tc*4];
            #pragma unroll
            for (int i = 0; i < 8; i++) {
                float sv = Ss[tr*8+i][jr];
                accy[i][0] += sv * br[0];
                accy[i][1] += sv * br[1];
                accy[i][2] += sv * br[2];
                accy[i][3] += sv * br[3];
            }
        }
    }

    // store y tile + accumulate GN partials from registers
    float ps = 0.f, ps2 = 0.f;
    float* ybase = y + ((size_t)(b*TT + i0))*DM + h*DH;
    #pragma unroll
    for (int i = 0; i < 8; i++) {
        #pragma unroll
        for (int j = 0; j < 4; j++) {
            ps  += accy[i][j];
            ps2 += accy[i][j] * accy[i][j];
        }
        *(float4*)(ybase + (size_t)(tr*8 + i)*DM + tc*4) =
            make_float4(accy[i][0], accy[i][1], accy[i][2], accy[i][3]);
    }
    // block reduce (warp shuffle + smem; smem reuse is safe after syncthreads)
    #pragma unroll
    for (int o = 16; o > 0; o >>= 1) {
        ps  += __shfl_down_sync(0xffffffffu, ps,  o);
        ps2 += __shfl_down_sync(0xffffffffu, ps2, o);
    }
    __syncthreads();
    float* rs  = smf;        // 8 floats
    float* rs2 = smf + 8;
    const int wid = tid >> 5, lid = tid & 31;
    if (lid == 0) { rs[wid] = ps; rs2[wid] = ps2; }
    __syncthreads();
    if (tid == 0) {
        float s = 0.f, s2 = 0.f;
        #pragma unroll
        for (int i = 0; i < 8; i++) { s += rs[i]; s2 += rs2[i]; }
        part[(bh*NC + it)*2]   = s;
        part[(bh*NC + it)*2+1] = s2;
    }
}

// ============================================================
// fused: stats from NC partials + normalize + bf16 split
// ============================================================
__global__ void gn_apply_split(const float* __restrict__ y, const float* __restrict__ part,
                               const float* __restrict__ gw, const float* __restrict__ gb,
                               __nv_bfloat16* __restrict__ hi, __nv_bfloat16* __restrict__ lo)
{
    size_t e = ((size_t)blockIdx.x * blockDim.x + threadIdx.x) * 4;
    int col = (int)(e % DM);
    size_t row = e / DM;
    int b = (int)(row / TT);
    int g = b * 16 + (col >> 6);
    float s = 0.f, s2 = 0.f;
    #pragma unroll
    for (int i = 0; i < NC; i++) {
        s  += part[(g*NC + i)*2];
        s2 += part[(g*NC + i)*2+1];
    }
    const float invN = 1.f / (float)(TT * DH);
    float mean = s * invN;
    float rstd = rsqrtf(s2 * invN - mean * mean + 1e-5f);
    float4 vv = *(const float4*)(y + e);
    float4 w4 = *(const float4*)(gw + col);
    float4 b4 = *(const float4*)(gb + col);
    float o0 = (vv.x - mean) * rstd * w4.x + b4.x;
    float o1 = (vv.y - mean) * rstd * w4.y + b4.y;
    float o2 = (vv.z - mean) * rstd * w4.z + b4.z;
    float o3 = (vv.w - mean) * rstd * w4.w + b4.w;
    __nv_bfloat16 h0, h1, h2, h3, l0, l1, l2, l3;
    split1(o0, h0, l0); split1(o1, h1, l1);
    split1(o2, h2, l2); split1(o3, h3, l3);
    __nv_bfloat162* hp = (__nv_bfloat162*)(hi + e);
    __nv_bfloat162* lp = (__nv_bfloat162*)(lo + e);
    hp[0] = __nv_bfloat162(h0, h1); hp[1] = __nv_bfloat162(h2, h3);
    lp[0] = __nv_bfloat162(l0, l1); lp[1] = __nv_bfloat162(l2, l3);
}

// ============================================================
extern "C" void kernel_launch(void* const* d_in, const int* in_sizes, int n_in,
                              void* d_out, int out_size)
{
    const float* x  = (const float*)d_in[0];
    const float* Wq = (const float*)d_in[1];
    const float* Wk = (const float*)d_in[2];
    const float* Wv = (const float*)d_in[3];
    const float* Wo = (const float*)d_in[4];
    const float* gw = (const float*)d_in[5];
    const float* gb = (const float*)d_in[6];
    float* out = (float*)d_out;

    float *q, *k, *v, *y, *pt, *P2, *S;
    __nv_bfloat16 *ah, *al, *wh, *wl;
    cudaGetSymbolAddress((void**)&q,  g_q);
    cudaGetSymbolAddress((void**)&k,  g_k);
    cudaGetSymbolAddress((void**)&v,  g_v);
    cudaGetSymbolAddress((void**)&y,  g_y);
    cudaGetSymbolAddress((void**)&pt, g_part);
    cudaGetSymbolAddress((void**)&P2, g_P2);
    cudaGetSymbolAddress((void**)&S,  g_S);
    cudaGetSymbolAddress((void**)&ah, g_ah);
    cudaGetSymbolAddress((void**)&al, g_al);
    cudaGetSymbolAddress((void**)&wh, g_wh);
    cudaGetSymbolAddress((void**)&wl, g_wl);

    const int ret_smem = RET_SMEM_FLOATS * (int)sizeof(float);
    cudaFuncSetAttribute(retention_chunk, cudaFuncAttributeMaxDynamicSharedMemorySize, ret_smem);
    cudaFuncSetAttribute(gemm_mma, cudaFuncAttributeMaxDynamicSharedMemorySize, GSM_BYTES);

    // one merged split launch (x + 4 weights)
    split_all<<<dim3(1024, 8), 256>>>(x, Wq, Wk, Wv, Wo, ah, al, wh, wl);

    // batched QKV GEMM
    dim3 gq(DM/128, MT/128, 3);
    gemm_mma<<<gq, 256, GSM_BYTES>>>(ah, al, wh, wl, q, k, v, MT, DM, DM, 0);

    chunk_state<<<dim3(NC, BB*NH, 2), 256>>>(k, v, P2);
    state_scan<<<dim3(16, BB*NH), 256>>>(P2, S);
    retention_chunk<<<dim3(NC, BB*NH), 256, ret_smem>>>(q, k, v, S, y, pt);

    gn_apply_split<<<(MT*DM)/(4*256), 256>>>(y, pt, gw, gb, ah, al);

    // output GEMM (weight index 3)
    dim3 go(DM/128, MT/128, 1);
    gemm_mma<<<go, 256, GSM_BYTES>>>(ah, al, wh, wl, out, out, out, MT, DM, DM, 3);
}

// round 15
// speedup vs baseline: 1.5617x; 1.5617x over previous
#include <cuda_runtime.h>
#include <cuda_bf16.h>
#include <cstdint>

#define DM 1024
#define NH 16
#define DH 64
#define BB 2
#define TT 2048
#define MT (BB*TT)    // 4096 rows total
#define CH 128        // chunk size
#define NC (TT/CH)    // 16 chunks

// ---- scratch (no allocations allowed) ----
__device__ float g_q[MT*DM];
__device__ float g_k[MT*DM];
__device__ float g_v[MT*DM];
__device__ float g_y[MT*DM];
__device__ float g_part[BB*NH*8*2];
__device__ float g_P2[BB*NH*NC*2*DH*DH];  // split-K partial states (2 halves)
__device__ float g_S[BB*NH*NC*DH*DH];
__device__ __nv_bfloat16 g_ah[MT*DM];     // activation hi
__device__ __nv_bfloat16 g_al[MT*DM];     // activation lo
__device__ __nv_bfloat16 g_wh[4*DM*DM];   // weight hi (q,k,v,o)
__device__ __nv_bfloat16 g_wl[4*DM*DM];   // weight lo

// ============================================================
// helpers
// ============================================================
__device__ __forceinline__ uint32_t smem_u32(const void* p) {
    uint32_t a;
    asm("{ .reg .u64 t; cvta.to.shared.u64 t, %1; cvt.u32.u64 %0, t; }" : "=r"(a) : "l"(p));
    return a;
}

#define CP16(smem_addr, gptr) \
    asm volatile("cp.async.cg.shared.global [%0], [%1], 16;" :: "r"(smem_addr), "l"(gptr))

__device__ __forceinline__ void ldmx4(uint32_t* r, uint32_t addr) {
    asm volatile("ldmatrix.sync.aligned.m8n8.x4.shared.b16 {%0,%1,%2,%3}, [%4];"
        : "=r"(r[0]), "=r"(r[1]), "=r"(r[2]), "=r"(r[3]) : "r"(addr));
}

__device__ __forceinline__ void mma16816(float* d, const uint32_t* a, uint32_t b0, uint32_t b1) {
    asm volatile("mma.sync.aligned.m16n8k16.row.col.f32.bf16.bf16.f32 "
        "{%0,%1,%2,%3}, {%4,%5,%6,%7}, {%8,%9}, {%0,%1,%2,%3};"
        : "+f"(d[0]), "+f"(d[1]), "+f"(d[2]), "+f"(d[3])
        : "r"(a[0]), "r"(a[1]), "r"(a[2]), "r"(a[3]), "r"(b0), "r"(b1));
}

__device__ __forceinline__ void split1(float x, __nv_bfloat16& h, __nv_bfloat16& l) {
    h = __float2bfloat16(x);
    l = __float2bfloat16(x - __bfloat162float(h));
}

// ============================================================
// merged split: one launch covers x (4 quarters) + 4 weights.
// ============================================================
__global__ void split_all(const float* __restrict__ x,
                          const float* __restrict__ Wq, const float* __restrict__ Wk,
                          const float* __restrict__ Wv, const float* __restrict__ Wo,
                          __nv_bfloat16* __restrict__ ah, __nv_bfloat16* __restrict__ al,
                          __nv_bfloat16* __restrict__ wh, __nv_bfloat16* __restrict__ wl)
{
    const int yy = blockIdx.y;
    const size_t i = (size_t)blockIdx.x * blockDim.x + threadIdx.x;
    const size_t e = i * 4;
    const float* src;
    __nv_bfloat16 *hp, *lp;
    if (yy < 4) {
        src = x  + (size_t)yy * (MT*DM/4) + e;
        hp  = ah + (size_t)yy * (MT*DM/4) + e;
        lp  = al + (size_t)yy * (MT*DM/4) + e;
    } else {
        const float* ws[4] = {Wq, Wk, Wv, Wo};
        src = ws[yy-4] + e;
        hp  = wh + (size_t)(yy-4) * DM*DM + e;
        lp  = wl + (size_t)(yy-4) * DM*DM + e;
    }
    float4 xx = *(const float4*)src;
    __nv_bfloat16 h0, h1, h2, h3, l0, l1, l2, l3;
    split1(xx.x, h0, l0); split1(xx.y, h1, l1);
    split1(xx.z, h2, l2); split1(xx.w, h3, l3);
    ((__nv_bfloat162*)hp)[0] = __nv_bfloat162(h0, h1);
    ((__nv_bfloat162*)hp)[1] = __nv_bfloat162(h2, h3);
    ((__nv_bfloat162*)lp)[0] = __nv_bfloat162(l0, l1);
    ((__nv_bfloat162*)lp)[1] = __nv_bfloat162(l2, l3);
}

// ============================================================
// HMMA bf16 GEMM with Ootomo split; batched over blockIdx.z.
// ============================================================
#define GSM_BYTES (2*4*128*40*2)   // 81920

__global__ __launch_bounds__(256, 2)
void gemm_mma(const __nv_bfloat16* __restrict__ Ah, const __nv_bfloat16* __restrict__ Al,
              const __nv_bfloat16* __restrict__ Wh, const __nv_bfloat16* __restrict__ Wl,
              float* __restrict__ C0, float* __restrict__ C1, float* __restrict__ C2,
              int M, int N, int K, int wbase)
{
    extern __shared__ __nv_bfloat16 smh[];
    const uint32_t sbase = smem_u32(smh);
    const int tid = threadIdx.x;
    const int lane = tid & 31;
    const int w = tid >> 5;
    const int wr = w >> 2;
    const int wc = w & 3;
    const int m0 = blockIdx.y * 128;
    const int n0 = blockIdx.x * 128;
    const int z = blockIdx.z;

    float* C = (z == 0) ? C0 : (z == 1) ? C1 : C2;
    const size_t woff = (size_t)(wbase + z) * DM * DM;
    const __nv_bfloat16* Bh = Wh + woff;
    const __nv_bfloat16* Bl = Wl + woff;

    const int lrow = tid >> 2;
    const int lc16 = tid & 3;

    const __nv_bfloat16* gsrc[4] = {Ah, Al, Bh, Bl};

    float acc[4][4][4];
    #pragma unroll
    for (int m = 0; m < 4; m++)
        #pragma unroll
        for (int n = 0; n < 4; n++)
            #pragma unroll
            for (int e = 0; e < 4; e++) acc[m][n][e] = 0.f;

    const int NCH = K >> 5;

    auto load_stage = [&](int s, int k0) {
        uint32_t sb = sbase + (uint32_t)s * 20480u * 2u;
        #pragma unroll
        for (int arr = 0; arr < 4; arr++) {
            const __nv_bfloat16* g = gsrc[arr];
            int base_row = (arr < 2) ? m0 : n0;
            #pragma unroll
            for (int half = 0; half < 2; half++) {
                int row = lrow + half * 64;
                uint32_t so = sb + (uint32_t)(arr * 5120 + row * 40 + lc16 * 8) * 2u;
                const __nv_bfloat16* gp = g + (size_t)(base_row + row) * K + k0 + lc16 * 8;
                CP16(so, gp);
            }
        }
    };

    load_stage(0, 0);
    asm volatile("cp.async.commit_group;" ::: "memory");

    for (int c = 0; c < NCH; ++c) {
        const int s = c & 1;
        if (c + 1 < NCH) {
            load_stage(s ^ 1, (c + 1) << 5);
            asm volatile("cp.async.commit_group;" ::: "memory");
            asm volatile("cp.async.wait_group 1;" ::: "memory");
        } else {
            asm volatile("cp.async.wait_group 0;" ::: "memory");
        }
        __syncthreads();

        const uint32_t sb = sbase + (uint32_t)s * 20480u * 2u;
        const uint32_t sA  = sb;
        const uint32_t sAl = sb + 5120u * 2u;
        const uint32_t sB  = sb + 10240u * 2u;
        const uint32_t sBl = sb + 15360u * 2u;

        #pragma unroll
        for (int kk = 0; kk < 2; ++kk) {
            const int kb = kk * 16;
            uint32_t ah4[4][4], al4[4][4];
            const uint32_t arow = (uint32_t)(wr * 64 + (lane & 15));
            const uint32_t acol = (uint32_t)(kb + (lane >> 4) * 8);
            #pragma unroll
            for (int m = 0; m < 4; m++) {
                uint32_t off = ((arow + m * 16) * 40u + acol) * 2u;
                ldmx4(ah4[m], sA  + off);
                ldmx4(al4[m], sAl + off);
            }
            uint32_t bh4[2][4], bl4[2][4];
            const uint32_t brow = (uint32_t)(wc * 32 + (lane & 7) + ((lane >> 4) << 3));
            const uint32_t bcol = (uint32_t)(kb + ((lane >> 3) & 1) * 8);
            #pragma unroll
            for (int p = 0; p < 2; p++) {
                uint32_t off = ((brow + p * 16) * 40u + bcol) * 2u;
                ldmx4(bh4[p], sB  + off);
                ldmx4(bl4[p], sBl + off);
            }
            #pragma unroll
            for (int m = 0; m < 4; m++) {
                #pragma unroll
                for (int n = 0; n < 4; n++) {
                    uint32_t b0 = bh4[n >> 1][(n & 1) * 2];
                    uint32_t b1 = bh4[n >> 1][(n & 1) * 2 + 1];
                    uint32_t c0 = bl4[n >> 1][(n & 1) * 2];
                    uint32_t c1 = bl4[n >> 1][(n & 1) * 2 + 1];
                    mma16816(acc[m][n], ah4[m], b0, b1);
                    mma16816(acc[m][n], ah4[m], c0, c1);
                    mma16816(acc[m][n], al4[m], b0, b1);
                }
            }
        }
        __syncthreads();
    }

    const int r0 = m0 + wr * 64 + (lane >> 2);
    const int cc = n0 + wc * 32 + (lane & 3) * 2;
    #pragma unroll
    for (int m = 0; m < 4; m++) {
        #pragma unroll
        for (int n = 0; n < 4; n++) {
            float* p0 = C + (size_t)(r0 + m * 16) * N + cc + n * 8;
            float* p1 = C + (size_t)(r0 + m * 16 + 8) * N + cc + n * 8;
            *(float2*)p0 = make_float2(acc[m][n][0], acc[m][n][1]);
            *(float2*)p1 = make_float2(acc[m][n][2], acc[m][n][3]);
        }
    }
}

// ============================================================
// chunk_state split-K: grid (NC, BH, 2); each block does 64 j-rows
// ============================================================
__global__ __launch_bounds__(256)
void chunk_state(const float* __restrict__ kmat, const float* __restrict__ vmat,
                 float* __restrict__ P2)
{
    __shared__ float Ks[64][68];
    __shared__ float Vs[64][68];
    const int ch = blockIdx.x;
    const int bh = blockIdx.y;
    const int z  = blockIdx.z;
    const int b = bh >> 4, h = bh & 15;
    const float lg = log2f(1.f - exp2f(-5.f - (float)h));
    const int tid = threadIdx.x;
    const int j0 = ch * CH + z * 64;

    const float* kbase = kmat + ((size_t)(b*TT + j0))*DM + h*DH;
    const float* vbase = vmat + ((size_t)(b*TT + j0))*DM + h*DH;
    for (int s = tid; s < 64*16; s += 256) {
        int row = s >> 4, c4 = (s & 15) << 2;
        float sc = exp2f(lg * (float)(CH - z*64 - row));
        float4 kk = *(const float4*)(kbase + (size_t)row*DM + c4);
        Ks[row][c4+0] = kk.x*sc; Ks[row][c4+1] = kk.y*sc;
        Ks[row][c4+2] = kk.z*sc; Ks[row][c4+3] = kk.w*sc;
        float4 vv = *(const float4*)(vbase + (size_t)row*DM + c4);
        *(float4*)&Vs[row][c4] = vv;
    }
    __syncthreads();

    const int tr = tid >> 4, tc = tid & 15;
    float acc[4][4];
    #pragma unroll
    for (int i = 0; i < 4; i++)
        #pragma unroll
        for (int j = 0; j < 4; j++) acc[i][j] = 0.f;

    #pragma unroll 4
    for (int j = 0; j < 64; j++) {
        float ar[4], br[4];
        *(float4*)&ar[0] = *(const float4*)&Ks[j][tr*4];
        *(float4*)&br[0] = *(const float4*)&Vs[j][tc*4];
        #pragma unroll
        for (int i = 0; i < 4; i++)
            #pragma unroll
            for (int jj = 0; jj < 4; jj++)
                acc[i][jj] += ar[i] * br[jj];
    }

    float* pbase = P2 + ((size_t)((bh*NC + ch)*2 + z))*DH*DH;
    #pragma unroll
    for (int i = 0; i < 4; i++)
        *(float4*)(pbase + (tr*4 + i)*DH + tc*4) =
            make_float4(acc[i][0], acc[i][1], acc[i][2], acc[i][3]);
}

// ============================================================
// state_scan: parallel over elements.
// ============================================================
__global__ __launch_bounds__(256)
void state_scan(const float* __restrict__ P2, float* __restrict__ S)
{
    const int bh = blockIdx.y;
    const int e = blockIdx.x * 256 + threadIdx.x;   // 0..4095
    const int h = bh & 15;
    const float lg = log2f(1.f - exp2f(-5.f - (float)h));
    const float gC = exp2f(lg * (float)CH);

    float s = 0.f;
    #pragma unroll
    for (int n = 0; n < NC; n++) {
        const size_t sb = ((size_t)(bh*NC + n))*DH*DH;
        const size_t pb = ((size_t)(bh*NC + n))*2*DH*DH;
        S[sb + e] = s * 0.125f;
        float p0 = P2[pb + e];
        float p1 = P2[pb + DH*DH + e];
        s = gC * s + p0 + p1;
    }
}

// ============================================================
// retention_chunk (proven R11 version, reg-capped)
// ============================================================
#define RET_SMEM_FLOATS (64*132 + 64*68 + 64*68 + 128*68)

__global__ __launch_bounds__(256, 2)
void retention_chunk(const float* __restrict__ q, const float* __restrict__ kmat,
                     const float* __restrict__ vmat, const float* __restrict__ Sg,
                     float* __restrict__ y)
{
    extern __shared__ float smf[];
    float (*QT)[132] = (float (*)[132])smf;
    float (*KT)[68]  = (float (*)[68])(smf + 64*132);
    float (*Vs)[68]  = (float (*)[68])(smf + 64*132 + 64*68);
    float (*Ss)[68]  = (float (*)[68])(smf + 64*132 + 2*64*68);

    const int it = blockIdx.x;
    const int bh = blockIdx.y;
    const int b = bh >> 4, h = bh & 15;
    const int i0 = it * CH;
    const float lg = log2f(1.f - exp2f(-5.f - (float)h));
    const int tid = threadIdx.x;
    const int tr = tid >> 4;
    const int tc = tid & 15;

    const float* qbase = q + ((size_t)(b*TT + i0))*DM + h*DH;
    for (int s = tid; s < CH*16; s += 256) {
        int row = s >> 4, c4 = (s & 15) << 2;
        float4 a = *(const float4*)(qbase + (size_t)row*DM + c4);
        float sc = exp2f(lg * (float)row);
        QT[c4+0][row] = a.x*sc; QT[c4+1][row] = a.y*sc;
        QT[c4+2][row] = a.z*sc; QT[c4+3][row] = a.w*sc;
    }
    const float* sbase = Sg + ((size_t)(bh*NC + it))*DH*DH;
    for (int s = tid; s < 64*16; s += 256) {
        int row = s >> 4, c4 = (s & 15) << 2;
        *(float4*)&KT[row][c4] = *(const float4*)(sbase + row*DH + c4);
    }
    __syncthreads();

    float accy[8][4];
    #pragma unroll
    for (int i = 0; i < 8; i++)
        #pragma unroll
        for (int j = 0; j < 4; j++) accy[i][j] = 0.f;

    #pragma unroll 8
    for (int a = 0; a < DH; a++) {
        float ar[8], br[4];
        *(float4*)&ar[0] = *(const float4*)&QT[a][tr*8];
        *(float4*)&ar[4] = *(const float4*)&QT[a][tr*8+4];
        *(float4*)&br[0] = *(const float4*)&KT[a][tc*4];
        #pragma unroll
        for (int i = 0; i < 8; i++)
            #pragma unroll
            for (int j = 0; j < 4; j++)
                accy[i][j] += ar[i] * br[j];
    }

    #pragma unroll
    for (int jt = 0; jt < 2; jt++) {
        const int j0 = i0 + (jt << 6);
        const int diffbase = -(jt << 6);
        const float* kbase = kmat + ((size_t)(b*TT + j0))*DM + h*DH;
        const float* vbase = vmat + ((size_t)(b*TT + j0))*DM + h*DH;
        __syncthreads();
        for (int s = tid; s < 64*16; s += 256) {
            int row = s >> 4, c4 = (s & 15) << 2;
            float sc = exp2f(-lg * (float)row);
            float4 kk = *(const float4*)(kbase + (size_t)row*DM + c4);
            KT[c4+0][row] = kk.x*sc; KT[c4+1][row] = kk.y*sc;
            KT[c4+2][row] = kk.z*sc; KT[c4+3][row] = kk.w*sc;
            float4 vv = *(const float4*)(vbase + (size_t)row*DM + c4);
            *(float4*)&Vs[row][c4] = vv;
        }
        __syncthreads();

        float acc1[8][4];
        #pragma unroll
        for (int i = 0; i < 8; i++)
            #pragma unroll
            for (int j = 0; j < 4; j++) acc1[i][j] = 0.f;
        #pragma unroll 8
        for (int c = 0; c < DH; c++) {
            float ar[8], br[4];
            *(float4*)&ar[0] = *(const float4*)&QT[c][tr*8];
            *(float4*)&ar[4] = *(const float4*)&QT[c][tr*8+4];
            *(float4*)&br[0] = *(const float4*)&KT[c][tc*4];
            #pragma unroll
            for (int i = 0; i < 8; i++)
                #pragma unroll
                for (int j = 0; j < 4; j++)
                    acc1[i][j] += ar[i] * br[j];
        }

        const float base = exp2f(lg * (float)diffbase) * 0.125f;
        #pragma unroll
        for (int i = 0; i < 8; i++) {
            const int ir = tr*8 + i;
            float o0 = acc1[i][0]*base, o1 = acc1[i][1]*base;
            float o2 = acc1[i][2]*base, o3 = acc1[i][3]*base;
            int d0 = diffbase + ir - (tc*4);
            if (d0     < 0) o0 = 0.f;
            if (d0 - 1 < 0) o1 = 0.f;
            if (d0 - 2 < 0) o2 = 0.f;
            if (d0 - 3 < 0) o3 = 0.f;
            *(float4*)&Ss[ir][tc*4] = make_float4(o0, o1, o2, o3);
        }
        __syncthreads();

        #pragma unroll 8
        for (int jr = 0; jr < 64; jr++) {
            float br[4];
            *(float4*)&br[0] = *(const float4*)&Vs[jr][tc*4];
            #pragma unroll
            for (int i = 0; i < 8; i++) {
                float sv = Ss[tr*8+i][jr];
                accy[i][0] += sv * br[0];
                accy[i][1] += sv * br[1];
                accy[i][2] += sv * br[2];
                accy[i][3] += sv * br[3];
            }
        }
    }

    float* ybase = y + ((size_t)(b*TT + i0))*DM + h*DH;
    #pragma unroll
    for (int i = 0; i < 8; i++) {
        *(float4*)(ybase + (size_t)(tr*8 + i)*DM + tc*4) =
            make_float4(accy[i][0], accy[i][1], accy[i][2], accy[i][3]);
    }
}

// ============================================================
// GroupNorm: phase-1 partial reduce + fused (stats + apply + split)
// ============================================================
__global__ void gn_reduce1(const float* __restrict__ y, float* __restrict__ part)
{
    const int bh = blockIdx.x;
    const int slab = blockIdx.y;
    const int b = bh >> 4, h = bh & 15;
    const float* base = y + (size_t)b*TT*DM + (size_t)slab*(TT/8)*DM + h*DH;
    float s = 0.f, s2 = 0.f;
    for (int sl = threadIdx.x; sl < (TT/8)*16; sl += blockDim.x) {
        int t = sl >> 4, c4 = (sl & 15) << 2;
        float4 vv = *(const float4*)(base + (size_t)t*DM + c4);
        s  += vv.x + vv.y + vv.z + vv.w;
        s2 += vv.x*vv.x + vv.y*vv.y + vv.z*vv.z + vv.w*vv.w;
    }
    #pragma unroll
    for (int o = 16; o > 0; o >>= 1) {
        s  += __shfl_down_sync(0xffffffffu, s,  o);
        s2 += __shfl_down_sync(0xffffffffu, s2, o);
    }
    __shared__ float rs[32], rs2[32];
    const int wid = threadIdx.x >> 5, lid = threadIdx.x & 31;
    if (lid == 0) { rs[wid] = s; rs2[wid] = s2; }
    __syncthreads();
    if (wid == 0) {
        const int nw = blockDim.x >> 5;
        s  = (lid < nw) ? rs[lid]  : 0.f;
        s2 = (lid < nw) ? rs2[lid] : 0.f;
        #pragma unroll
        for (int o = 16; o > 0; o >>= 1) {
            s  += __shfl_down_sync(0xffffffffu, s,  o);
            s2 += __shfl_down_sync(0xffffffffu, s2, o);
        }
        if (lid == 0) {
            part[(bh*8 + slab)*2]   = s;
            part[(bh*8 + slab)*2+1] = s2;
        }
    }
}

__global__ void gn_apply_split(const float* __restrict__ y, const float* __restrict__ part,
                               const float* __restrict__ gw, const float* __restrict__ gb,
                               __nv_bfloat16* __restrict__ hi, __nv_bfloat16* __restrict__ lo)
{
    size_t e = ((size_t)blockIdx.x * blockDim.x + threadIdx.x) * 4;
    int col = (int)(e % DM);
    size_t row = e / DM;
    int b = (int)(row / TT);
    int g = b * 16 + (col >> 6);
    float s = 0.f, s2 = 0.f;
    #pragma unroll
    for (int i = 0; i < 8; i++) {
        s  += part[(g*8 + i)*2];
        s2 += part[(g*8 + i)*2+1];
    }
    const float invN = 1.f / (float)(TT * DH);
    float mean = s * invN;
    float rstd = rsqrtf(s2 * invN - mean * mean + 1e-5f);
    float4 vv = *(const float4*)(y + e);
    float4 w4 = *(const float4*)(gw + col);
    float4 b4 = *(const float4*)(gb + col);
    float o0 = (vv.x - mean) * rstd * w4.x + b4.x;
    float o1 = (vv.y - mean) * rstd * w4.y + b4.y;
    float o2 = (vv.z - mean) * rstd * w4.z + b4.z;
    float o3 = (vv.w - mean) * rstd * w4.w + b4.w;
    __nv_bfloat16 h0, h1, h2, h3, l0, l1, l2, l3;
    split1(o0, h0, l0); split1(o1, h1, l1);
    split1(o2, h2, l2); split1(o3, h3, l3);
    __nv_bfloat162* hp = (__nv_bfloat162*)(hi + e);
    __nv_bfloat162* lp = (__nv_bfloat162*)(lo + e);
    hp[0] = __nv_bfloat162(h0, h1); hp[1] = __nv_bfloat162(h2, h3);
    lp[0] = __nv_bfloat162(l0, l1); lp[1] = __nv_bfloat162(l2, l3);
}

// ============================================================
extern "C" void kernel_launch(void* const* d_in, const int* in_sizes, int n_in,
                              void* d_out, int out_size)
{
    const float* x  = (const float*)d_in[0];
    const float* Wq = (const float*)d_in[1];
    const float* Wk = (const float*)d_in[2];
    const float* Wv = (const float*)d_in[3];
    const float* Wo = (const float*)d_in[4];
    const float* gw = (const float*)d_in[5];
    const float* gb = (const float*)d_in[6];
    float* out = (float*)d_out;

    float *q, *k, *v, *y, *pt, *P2, *S;
    __nv_bfloat16 *ah, *al, *wh, *wl;
    cudaGetSymbolAddress((void**)&q,  g_q);
    cudaGetSymbolAddress((void**)&k,  g_k);
    cudaGetSymbolAddress((void**)&v,  g_v);
    cudaGetSymbolAddress((void**)&y,  g_y);
    cudaGetSymbolAddress((void**)&pt, g_part);
    cudaGetSymbolAddress((void**)&P2, g_P2);
    cudaGetSymbolAddress((void**)&S,  g_S);
    cudaGetSymbolAddress((void**)&ah, g_ah);
    cudaGetSymbolAddress((void**)&al, g_al);
    cudaGetSymbolAddress((void**)&wh, g_wh);
    cudaGetSymbolAddress((void**)&wl, g_wl);

    const int ret_smem = RET_SMEM_FLOATS * (int)sizeof(float);
    cudaFuncSetAttribute(retention_chunk, cudaFuncAttributeMaxDynamicSharedMemorySize, ret_smem);
    cudaFuncSetAttribute(gemm_mma, cudaFuncAttributeMaxDynamicSharedMemorySize, GSM_BYTES);

    // one merged split launch (x + 4 weights)
    split_all<<<dim3(1024, 8), 256>>>(x, Wq, Wk, Wv, Wo, ah, al, wh, wl);

    // batched QKV GEMM
    dim3 gq(DM/128, MT/128, 3);
    gemm_mma<<<gq, 256, GSM_BYTES>>>(ah, al, wh, wl, q, k, v, MT, DM, DM, 0);

    chunk_state<<<dim3(NC, BB*NH, 2), 256>>>(k, v, P2);
    state_scan<<<dim3(16, BB*NH), 256>>>(P2, S);
    retention_chunk<<<dim3(NC, BB*NH), 256, ret_smem>>>(q, k, v, S, y);

    gn_reduce1<<<dim3(BB*NH, 8), 512>>>(y, pt);
    gn_apply_split<<<(MT*DM)/(4*256), 256>>>(y, pt, gw, gb, ah, al);

    // output GEMM (weight index 3)
    dim3 go(DM/128, MT/128, 1);
    gemm_mma<<<go, 256, GSM_BYTES>>>(ah, al, wh, wl, out, out, out, MT, DM, DM, 3);
}

// round 16
// speedup vs baseline: 2.0040x; 1.2832x over previous
#include <cuda_runtime.h>
#include <cuda_fp16.h>
#include <cuda_bf16.h>
#include <cstdint>

#define DM 1024
#define NH 16
#define DH 64
#define BB 2
#define TT 2048
#define MT (BB*TT)    // 4096 rows total
#define CH 128        // chunk size
#define NC (TT/CH)    // 16 chunks

// ---- scratch (no allocations allowed) ----
__device__ float g_q[MT*DM];
__device__ float g_k[MT*DM];
__device__ float g_v[MT*DM];
__device__ float g_y[MT*DM];
__device__ float g_part[BB*NH*8*2];
__device__ float g_P2[BB*NH*NC*2*DH*DH];  // split-K partial states (2 halves)
__device__ float g_S[BB*NH*NC*DH*DH];
__device__ __half g_ah[MT*DM];     // activation fp16 (unsplit)
__device__ __half g_wh[4*DM*DM];   // weight hi (q,k,v,o)
__device__ __half g_wl[4*DM*DM];   // weight lo

// ============================================================
// helpers
// ============================================================
__device__ __forceinline__ uint32_t smem_u32(const void* p) {
    uint32_t a;
    asm("{ .reg .u64 t; cvta.to.shared.u64 t, %1; cvt.u32.u64 %0, t; }" : "=r"(a) : "l"(p));
    return a;
}

#define CP16(smem_addr, gptr) \
    asm volatile("cp.async.cg.shared.global [%0], [%1], 16;" :: "r"(smem_addr), "l"(gptr))

__device__ __forceinline__ void ldmx4(uint32_t* r, uint32_t addr) {
    asm volatile("ldmatrix.sync.aligned.m8n8.x4.shared.b16 {%0,%1,%2,%3}, [%4];"
        : "=r"(r[0]), "=r"(r[1]), "=r"(r[2]), "=r"(r[3]) : "r"(addr));
}

// fp16 inputs, fp32 accumulate
__device__ __forceinline__ void mma16816h(float* d, const uint32_t* a, uint32_t b0, uint32_t b1) {
    asm volatile("mma.sync.aligned.m16n8k16.row.col.f32.f16.f16.f32 "
        "{%0,%1,%2,%3}, {%4,%5,%6,%7}, {%8,%9}, {%0,%1,%2,%3};"
        : "+f"(d[0]), "+f"(d[1]), "+f"(d[2]), "+f"(d[3])
        : "r"(a[0]), "r"(a[1]), "r"(a[2]), "r"(a[3]), "r"(b0), "r"(b1));
}

__device__ __forceinline__ void split1h(float x, __half& h, __half& l) {
    h = __float2half_rn(x);
    l = __float2half_rn(x - __half2float(h));
}

// ============================================================
// merged split: one launch covers x (4 quarters, fp16 unsplit) + 4 weights (hi/lo).
// ============================================================
__global__ void split_all(const float* __restrict__ x,
                          const float* __restrict__ Wq, const float* __restrict__ Wk,
                          const float* __restrict__ Wv, const float* __restrict__ Wo,
                          __half* __restrict__ ah,
                          __half* __restrict__ wh, __half* __restrict__ wl)
{
    const int yy = blockIdx.y;
    const size_t i = (size_t)blockIdx.x * blockDim.x + threadIdx.x;
    const size_t e = i * 4;
    if (yy < 4) {
        const float* src = x + (size_t)yy * (MT*DM/4) + e;
        __half* hp = ah + (size_t)yy * (MT*DM/4) + e;
        float4 xx = *(const float4*)src;
        __half2* h2 = (__half2*)hp;
        h2[0] = __half2(__float2half_rn(xx.x), __float2half_rn(xx.y));
        h2[1] = __half2(__float2half_rn(xx.z), __float2half_rn(xx.w));
    } else {
        const float* ws[4] = {Wq, Wk, Wv, Wo};
        const float* src = ws[yy-4] + e;
        __half* hp = wh + (size_t)(yy-4) * DM*DM + e;
        __half* lp = wl + (size_t)(yy-4) * DM*DM + e;
        float4 xx = *(const float4*)src;
        __half h0, h1, h2v, h3, l0, l1, l2, l3;
        split1h(xx.x, h0, l0); split1h(xx.y, h1, l1);
        split1h(xx.z, h2v, l2); split1h(xx.w, h3, l3);
        ((__half2*)hp)[0] = __half2(h0, h1); ((__half2*)hp)[1] = __half2(h2v, h3);
        ((__half2*)lp)[0] = __half2(l0, l1); ((__half2*)lp)[1] = __half2(l2, l3);
    }
}

// ============================================================
// HMMA fp16 GEMM, 2-product compensated (A fp16, B = Bh+Bl).
// 128x128x32 tile, 8 warps, warp tile 64x32, cp.async x2 stages.
// smem halves: 3 arrays (A, Bh, Bl) stride 5120, stage stride 15360.
// ============================================================
#define GSM_BYTES (2*3*128*40*2)   // 61440

__global__ __launch_bounds__(256, 2)
void gemm_mma(const __half* __restrict__ Ah,
              const __half* __restrict__ Wh, const __half* __restrict__ Wl,
              float* __restrict__ C0, float* __restrict__ C1, float* __restrict__ C2,
              int M, int N, int K, int wbase)
{
    extern __shared__ __half smh[];
    const uint32_t sbase = smem_u32(smh);
    const int tid = threadIdx.x;
    const int lane = tid & 31;
    const int w = tid >> 5;
    const int wr = w >> 2;
    const int wc = w & 3;
    const int m0 = blockIdx.y * 128;
    const int n0 = blockIdx.x * 128;
    const int z = blockIdx.z;

    float* C = (z == 0) ? C0 : (z == 1) ? C1 : C2;
    const size_t woff = (size_t)(wbase + z) * DM * DM;
    const __half* Bh = Wh + woff;
    const __half* Bl = Wl + woff;

    const int lrow = tid >> 2;
    const int lc16 = tid & 3;

    const __half* gsrc[3] = {Ah, Bh, Bl};

    float acc[4][4][4];
    #pragma unroll
    for (int m = 0; m < 4; m++)
        #pragma unroll
        for (int n = 0; n < 4; n++)
            #pragma unroll
            for (int e = 0; e < 4; e++) acc[m][n][e] = 0.f;

    const int NCH = K >> 5;

    auto load_stage = [&](int s, int k0) {
        uint32_t sb = sbase + (uint32_t)s * 15360u * 2u;
        #pragma unroll
        for (int arr = 0; arr < 3; arr++) {
            const __half* g = gsrc[arr];
            int base_row = (arr == 0) ? m0 : n0;
            #pragma unroll
            for (int half = 0; half < 2; half++) {
                int row = lrow + half * 64;
                uint32_t so = sb + (uint32_t)(arr * 5120 + row * 40 + lc16 * 8) * 2u;
                const __half* gp = g + (size_t)(base_row + row) * K + k0 + lc16 * 8;
                CP16(so, gp);
            }
        }
    };

    load_stage(0, 0);
    asm volatile("cp.async.commit_group;" ::: "memory");

    for (int c = 0; c < NCH; ++c) {
        const int s = c & 1;
        if (c + 1 < NCH) {
            load_stage(s ^ 1, (c + 1) << 5);
            asm volatile("cp.async.commit_group;" ::: "memory");
            asm volatile("cp.async.wait_group 1;" ::: "memory");
        } else {
            asm volatile("cp.async.wait_group 0;" ::: "memory");
        }
        __syncthreads();

        const uint32_t sb = sbase + (uint32_t)s * 15360u * 2u;
        const uint32_t sA  = sb;
        const uint32_t sB  = sb + 5120u * 2u;
        const uint32_t sBl = sb + 10240u * 2u;

        #pragma unroll
        for (int kk = 0; kk < 2; ++kk) {
            const int kb = kk * 16;
            uint32_t ah4[4][4];
            const uint32_t arow = (uint32_t)(wr * 64 + (lane & 15));
            const uint32_t acol = (uint32_t)(kb + (lane >> 4) * 8);
            #pragma unroll
            for (int m = 0; m < 4; m++) {
                uint32_t off = ((arow + m * 16) * 40u + acol) * 2u;
                ldmx4(ah4[m], sA + off);
            }
            uint32_t bh4[2][4], bl4[2][4];
            const uint32_t brow = (uint32_t)(wc * 32 + (lane & 7) + ((lane >> 4) << 3));
            const uint32_t bcol = (uint32_t)(kb + ((lane >> 3) & 1) * 8);
            #pragma unroll
            for (int p = 0; p < 2; p++) {
                uint32_t off = ((brow + p * 16) * 40u + bcol) * 2u;
                ldmx4(bh4[p], sB  + off);
                ldmx4(bl4[p], sBl + off);
            }
            #pragma unroll
            for (int m = 0; m < 4; m++) {
                #pragma unroll
                for (int n = 0; n < 4; n++) {
                    uint32_t b0 = bh4[n >> 1][(n & 1) * 2];
                    uint32_t b1 = bh4[n >> 1][(n & 1) * 2 + 1];
                    uint32_t c0 = bl4[n >> 1][(n & 1) * 2];
                    uint32_t c1 = bl4[n >> 1][(n & 1) * 2 + 1];
                    mma16816h(acc[m][n], ah4[m], b0, b1);
                    mma16816h(acc[m][n], ah4[m], c0, c1);
                }
            }
        }
        __syncthreads();
    }

    const int r0 = m0 + wr * 64 + (lane >> 2);
    const int cc = n0 + wc * 32 + (lane & 3) * 2;
    #pragma unroll
    for (int m = 0; m < 4; m++) {
        #pragma unroll
        for (int n = 0; n < 4; n++) {
            float* p0 = C + (size_t)(r0 + m * 16) * N + cc + n * 8;
            float* p1 = C + (size_t)(r0 + m * 16 + 8) * N + cc + n * 8;
            *(float2*)p0 = make_float2(acc[m][n][0], acc[m][n][1]);
            *(float2*)p1 = make_float2(acc[m][n][2], acc[m][n][3]);
        }
    }
}

// ============================================================
// chunk_state split-K: grid (NC, BH, 2); each block does 64 j-rows
// ============================================================
__global__ __launch_bounds__(256)
void chunk_state(const float* __restrict__ kmat, const float* __restrict__ vmat,
                 float* __restrict__ P2)
{
    __shared__ float Ks[64][68];
    __shared__ float Vs[64][68];
    const int ch = blockIdx.x;
    const int bh = blockIdx.y;
    const int z  = blockIdx.z;
    const int b = bh >> 4, h = bh & 15;
    const float lg = log2f(1.f - exp2f(-5.f - (float)h));
    const int tid = threadIdx.x;
    const int j0 = ch * CH + z * 64;

    const float* kbase = kmat + ((size_t)(b*TT + j0))*DM + h*DH;
    const float* vbase = vmat + ((size_t)(b*TT + j0))*DM + h*DH;
    for (int s = tid; s < 64*16; s += 256) {
        int row = s >> 4, c4 = (s & 15) << 2;
        float sc = exp2f(lg * (float)(CH - z*64 - row));
        float4 kk = *(const float4*)(kbase + (size_t)row*DM + c4);
        Ks[row][c4+0] = kk.x*sc; Ks[row][c4+1] = kk.y*sc;
        Ks[row][c4+2] = kk.z*sc; Ks[row][c4+3] = kk.w*sc;
        float4 vv = *(const float4*)(vbase + (size_t)row*DM + c4);
        *(float4*)&Vs[row][c4] = vv;
    }
    __syncthreads();

    const int tr = tid >> 4, tc = tid & 15;
    float acc[4][4];
    #pragma unroll
    for (int i = 0; i < 4; i++)
        #pragma unroll
        for (int j = 0; j < 4; j++) acc[i][j] = 0.f;

    #pragma unroll 4
    for (int j = 0; j < 64; j++) {
        float ar[4], br[4];
        *(float4*)&ar[0] = *(const float4*)&Ks[j][tr*4];
        *(float4*)&br[0] = *(const float4*)&Vs[j][tc*4];
        #pragma unroll
        for (int i = 0; i < 4; i++)
            #pragma unroll
            for (int jj = 0; jj < 4; jj++)
                acc[i][jj] += ar[i] * br[jj];
    }

    float* pbase = P2 + ((size_t)((bh*NC + ch)*2 + z))*DH*DH;
    #pragma unroll
    for (int i = 0; i < 4; i++)
        *(float4*)(pbase + (tr*4 + i)*DH + tc*4) =
            make_float4(acc[i][0], acc[i][1], acc[i][2], acc[i][3]);
}

// ============================================================
// state_scan: parallel over elements.
// ============================================================
__global__ __launch_bounds__(256)
void state_scan(const float* __restrict__ P2, float* __restrict__ S)
{
    const int bh = blockIdx.y;
    const int e = blockIdx.x * 256 + threadIdx.x;   // 0..4095
    const int h = bh & 15;
    const float lg = log2f(1.f - exp2f(-5.f - (float)h));
    const float gC = exp2f(lg * (float)CH);

    float s = 0.f;
    #pragma unroll
    for (int n = 0; n < NC; n++) {
        const size_t sb = ((size_t)(bh*NC + n))*DH*DH;
        const size_t pb = ((size_t)(bh*NC + n))*2*DH*DH;
        S[sb + e] = s * 0.125f;
        float p0 = P2[pb + e];
        float p1 = P2[pb + DH*DH + e];
        s = gC * s + p0 + p1;
    }
}

// ============================================================
// retention_chunk (proven R11 version, reg-capped)
// ============================================================
#define RET_SMEM_FLOATS (64*132 + 64*68 + 64*68 + 128*68)

__global__ __launch_bounds__(256, 2)
void retention_chunk(const float* __restrict__ q, const float* __restrict__ kmat,
                     const float* __restrict__ vmat, const float* __restrict__ Sg,
                     float* __restrict__ y)
{
    extern __shared__ float smf[];
    float (*QT)[132] = (float (*)[132])smf;
    float (*KT)[68]  = (float (*)[68])(smf + 64*132);
    float (*Vs)[68]  = (float (*)[68])(smf + 64*132 + 64*68);
    float (*Ss)[68]  = (float (*)[68])(smf + 64*132 + 2*64*68);

    const int it = blockIdx.x;
    const int bh = blockIdx.y;
    const int b = bh >> 4, h = bh & 15;
    const int i0 = it * CH;
    const float lg = log2f(1.f - exp2f(-5.f - (float)h));
    const int tid = threadIdx.x;
    const int tr = tid >> 4;
    const int tc = tid & 15;

    const float* qbase = q + ((size_t)(b*TT + i0))*DM + h*DH;
    for (int s = tid; s < CH*16; s += 256) {
        int row = s >> 4, c4 = (s & 15) << 2;
        float4 a = *(const float4*)(qbase + (size_t)row*DM + c4);
        float sc = exp2f(lg * (float)row);
        QT[c4+0][row] = a.x*sc; QT[c4+1][row] = a.y*sc;
        QT[c4+2][row] = a.z*sc; QT[c4+3][row] = a.w*sc;
    }
    const float* sbase = Sg + ((size_t)(bh*NC + it))*DH*DH;
    for (int s = tid; s < 64*16; s += 256) {
        int row = s >> 4, c4 = (s & 15) << 2;
        *(float4*)&KT[row][c4] = *(const float4*)(sbase + row*DH + c4);
    }
    __syncthreads();

    float accy[8][4];
    #pragma unroll
    for (int i = 0; i < 8; i++)
        #pragma unroll
        for (int j = 0; j < 4; j++) accy[i][j] = 0.f;

    #pragma unroll 8
    for (int a = 0; a < DH; a++) {
        float ar[8], br[4];
        *(float4*)&ar[0] = *(const float4*)&QT[a][tr*8];
        *(float4*)&ar[4] = *(const float4*)&QT[a][tr*8+4];
        *(float4*)&br[0] = *(const float4*)&KT[a][tc*4];
        #pragma unroll
        for (int i = 0; i < 8; i++)
            #pragma unroll
            for (int j = 0; j < 4; j++)
                accy[i][j] += ar[i] * br[j];
    }

    #pragma unroll
    for (int jt = 0; jt < 2; jt++) {
        const int j0 = i0 + (jt << 6);
        const int diffbase = -(jt << 6);
        const float* kbase = kmat + ((size_t)(b*TT + j0))*DM + h*DH;
        const float* vbase = vmat + ((size_t)(b*TT + j0))*DM + h*DH;
        __syncthreads();
        for (int s = tid; s < 64*16; s += 256) {
            int row = s >> 4, c4 = (s & 15) << 2;
            float sc = exp2f(-lg * (float)row);
            float4 kk = *(const float4*)(kbase + (size_t)row*DM + c4);
            KT[c4+0][row] = kk.x*sc; KT[c4+1][row] = kk.y*sc;
            KT[c4+2][row] = kk.z*sc; KT[c4+3][row] = kk.w*sc;
            float4 vv = *(const float4*)(vbase + (size_t)row*DM + c4);
            *(float4*)&Vs[row][c4] = vv;
        }
        __syncthreads();

        float acc1[8][4];
        #pragma unroll
        for (int i = 0; i < 8; i++)
            #pragma unroll
            for (int j = 0; j < 4; j++) acc1[i][j] = 0.f;
        #pragma unroll 8
        for (int c = 0; c < DH; c++) {
            float ar[8], br[4];
            *(float4*)&ar[0] = *(const float4*)&QT[c][tr*8];
            *(float4*)&ar[4] = *(const float4*)&QT[c][tr*8+4];
            *(float4*)&br[0] = *(const float4*)&KT[c][tc*4];
            #pragma unroll
            for (int i = 0; i < 8; i++)
                #pragma unroll
                for (int j = 0; j < 4; j++)
                    acc1[i][j] += ar[i] * br[j];
        }

        const float base = exp2f(lg * (float)diffbase) * 0.125f;
        #pragma unroll
        for (int i = 0; i < 8; i++) {
            const int ir = tr*8 + i;
            float o0 = acc1[i][0]*base, o1 = acc1[i][1]*base;
            float o2 = acc1[i][2]*base, o3 = acc1[i][3]*base;
            int d0 = diffbase + ir - (tc*4);
            if (d0     < 0) o0 = 0.f;
            if (d0 - 1 < 0) o1 = 0.f;
            if (d0 - 2 < 0) o2 = 0.f;
            if (d0 - 3 < 0) o3 = 0.f;
            *(float4*)&Ss[ir][tc*4] = make_float4(o0, o1, o2, o3);
        }
        __syncthreads();

        #pragma unroll 8
        for (int jr = 0; jr < 64; jr++) {
            float br[4];
            *(float4*)&br[0] = *(const float4*)&Vs[jr][tc*4];
            #pragma unroll
            for (int i = 0; i < 8; i++) {
                float sv = Ss[tr*8+i][jr];
                accy[i][0] += sv * br[0];
                accy[i][1] += sv * br[1];
                accy[i][2] += sv * br[2];
                accy[i][3] += sv * br[3];
            }
        }
    }

    float* ybase = y + ((size_t)(b*TT + i0))*DM + h*DH;
    #pragma unroll
    for (int i = 0; i < 8; i++) {
        *(float4*)(ybase + (size_t)(tr*8 + i)*DM + tc*4) =
            make_float4(accy[i][0], accy[i][1], accy[i][2], accy[i][3]);
    }
}

// ============================================================
// GroupNorm: phase-1 partial reduce + fused (stats + apply + fp16 convert)
// ============================================================
__global__ void gn_reduce1(const float* __restrict__ y, float* __restrict__ part)
{
    const int bh = blockIdx.x;
    const int slab = blockIdx.y;
    const int b = bh >> 4, h = bh & 15;
    const float* base = y + (size_t)b*TT*DM + (size_t)slab*(TT/8)*DM + h*DH;
    float s = 0.f, s2 = 0.f;
    for (int sl = threadIdx.x; sl < (TT/8)*16; sl += blockDim.x) {
        int t = sl >> 4, c4 = (sl & 15) << 2;
        float4 vv = *(const float4*)(base + (size_t)t*DM + c4);
        s  += vv.x + vv.y + vv.z + vv.w;
        s2 += vv.x*vv.x + vv.y*vv.y + vv.z*vv.z + vv.w*vv.w;
    }
    #pragma unroll
    for (int o = 16; o > 0; o >>= 1) {
        s  += __shfl_down_sync(0xffffffffu, s,  o);
        s2 += __shfl_down_sync(0xffffffffu, s2, o);
    }
    __shared__ float rs[32], rs2[32];
    const int wid = threadIdx.x >> 5, lid = threadIdx.x & 31;
    if (lid == 0) { rs[wid] = s; rs2[wid] = s2; }
    __syncthreads();
    if (wid == 0) {
        const int nw = blockDim.x >> 5;
        s  = (lid < nw) ? rs[lid]  : 0.f;
        s2 = (lid < nw) ? rs2[lid] : 0.f;
        #pragma unroll
        for (int o = 16; o > 0; o >>= 1) {
            s  += __shfl_down_sync(0xffffffffu, s,  o);
            s2 += __shfl_down_sync(0xffffffffu, s2, o);
        }
        if (lid == 0) {
            part[(bh*8 + slab)*2]   = s;
            part[(bh*8 + slab)*2+1] = s2;
        }
    }
}

__global__ void gn_apply_split(const float* __restrict__ y, const float* __restrict__ part,
                               const float* __restrict__ gw, const float* __restrict__ gb,
                               __half* __restrict__ hi)
{
    size_t e = ((size_t)blockIdx.x * blockDim.x + threadIdx.x) * 4;
    int col = (int)(e % DM);
    size_t row = e / DM;
    int b = (int)(row / TT);
    int g = b * 16 + (col >> 6);
    float s = 0.f, s2 = 0.f;
    #pragma unroll
    for (int i = 0; i < 8; i++) {
        s  += part[(g*8 + i)*2];
        s2 += part[(g*8 + i)*2+1];
    }
    const float invN = 1.f / (float)(TT * DH);
    float mean = s * invN;
    float rstd = rsqrtf(s2 * invN - mean * mean + 1e-5f);
    float4 vv = *(const float4*)(y + e);
    float4 w4 = *(const float4*)(gw + col);
    float4 b4 = *(const float4*)(gb + col);
    float o0 = (vv.x - mean) * rstd * w4.x + b4.x;
    float o1 = (vv.y - mean) * rstd * w4.y + b4.y;
    float o2 = (vv.z - mean) * rstd * w4.z + b4.z;
    float o3 = (vv.w - mean) * rstd * w4.w + b4.w;
    __half2* hp = (__half2*)(hi + e);
    hp[0] = __half2(__float2half_rn(o0), __float2half_rn(o1));
    hp[1] = __half2(__float2half_rn(o2), __float2half_rn(o3));
}

// ============================================================
extern "C" void kernel_launch(void* const* d_in, const int* in_sizes, int n_in,
                              void* d_out, int out_size)
{
    const float* x  = (const float*)d_in[0];
    const float* Wq = (const float*)d_in[1];
    const float* Wk = (const float*)d_in[2];
    const float* Wv = (const float*)d_in[3];
    const float* Wo = (const float*)d_in[4];
    const float* gw = (const float*)d_in[5];
    const float* gb = (const float*)d_in[6];
    float* out = (float*)d_out;

    float *q, *k, *v, *y, *pt, *P2, *S;
    __half *ah, *wh, *wl;
    cudaGetSymbolAddress((void**)&q,  g_q);
    cudaGetSymbolAddress((void**)&k,  g_k);
    cudaGetSymbolAddress((void**)&v,  g_v);
    cudaGetSymbolAddress((void**)&y,  g_y);
    cudaGetSymbolAddress((void**)&pt, g_part);
    cudaGetSymbolAddress((void**)&P2, g_P2);
    cudaGetSymbolAddress((void**)&S,  g_S);
    cudaGetSymbolAddress((void**)&ah, g_ah);
    cudaGetSymbolAddress((void**)&wh, g_wh);
    cudaGetSymbolAddress((void**)&wl, g_wl);

    const int ret_smem = RET_SMEM_FLOATS * (int)sizeof(float);
    cudaFuncSetAttribute(retention_chunk, cudaFuncAttributeMaxDynamicSharedMemorySize, ret_smem);
    cudaFuncSetAttribute(gemm_mma, cudaFuncAttributeMaxDynamicSharedMemorySize, GSM_BYTES);

    // one merged split launch (x + 4 weights)
    split_all<<<dim3(1024, 8), 256>>>(x, Wq, Wk, Wv, Wo, ah, wh, wl);

    // batched QKV GEMM
    dim3 gq(DM/128, MT/128, 3);
    gemm_mma<<<gq, 256, GSM_BYTES>>>(ah, wh, wl, q, k, v, MT, DM, DM, 0);

    chunk_state<<<dim3(NC, BB*NH, 2), 256>>>(k, v, P2);
    state_scan<<<dim3(16, BB*NH), 256>>>(P2, S);
    retention_chunk<<<dim3(NC, BB*NH), 256, ret_smem>>>(q, k, v, S, y);

    gn_reduce1<<<dim3(BB*NH, 8), 512>>>(y, pt);
    gn_apply_split<<<(MT*DM)/(4*256), 256>>>(y, pt, gw, gb, ah);

    // output GEMM (weight index 3)
    dim3 go(DM/128, MT/128, 1);
    gemm_mma<<<go, 256, GSM_BYTES>>>(ah, wh, wl, out, out, out, MT, DM, DM, 3);
}

// round 17
// speedup vs baseline: 2.1503x; 1.0730x over previous
#include <cuda_runtime.h>
#include <cuda_fp16.h>
#include <cstdint>

#define DM 1024
#define NH 16
#define DH 64
#define BB 2
#define TT 2048
#define MT (BB*TT)    // 4096 rows total
#define CH 64         // chunk size (64-token chunks)
#define NC (TT/CH)    // 32 chunks

// ---- scratch (no allocations allowed) ----
__device__ float g_q[MT*DM];
__device__ float g_k[MT*DM];
__device__ float g_v[MT*DM];
__device__ float g_y[MT*DM];
__device__ float g_part[BB*NH*8*2];
__device__ float g_P[BB*NH*NC*DH*DH];     // per-chunk partial states
__device__ float g_S[BB*NH*NC*DH*DH];     // scanned states (pre-scaled 1/8)
__device__ __half g_ah[MT*DM];     // activation fp16 (unsplit)
__device__ __half g_wh[4*DM*DM];   // weight hi (q,k,v,o)
__device__ __half g_wl[4*DM*DM];   // weight lo

// ============================================================
// helpers
// ============================================================
__device__ __forceinline__ uint32_t smem_u32(const void* p) {
    uint32_t a;
    asm("{ .reg .u64 t; cvta.to.shared.u64 t, %1; cvt.u32.u64 %0, t; }" : "=r"(a) : "l"(p));
    return a;
}

#define CP16(smem_addr, gptr) \
    asm volatile("cp.async.cg.shared.global [%0], [%1], 16;" :: "r"(smem_addr), "l"(gptr))

__device__ __forceinline__ void ldmx4(uint32_t* r, uint32_t addr) {
    asm volatile("ldmatrix.sync.aligned.m8n8.x4.shared.b16 {%0,%1,%2,%3}, [%4];"
        : "=r"(r[0]), "=r"(r[1]), "=r"(r[2]), "=r"(r[3]) : "r"(addr));
}

__device__ __forceinline__ void mma16816h(float* d, const uint32_t* a, uint32_t b0, uint32_t b1) {
    asm volatile("mma.sync.aligned.m16n8k16.row.col.f32.f16.f16.f32 "
        "{%0,%1,%2,%3}, {%4,%5,%6,%7}, {%8,%9}, {%0,%1,%2,%3};"
        : "+f"(d[0]), "+f"(d[1]), "+f"(d[2]), "+f"(d[3])
        : "r"(a[0]), "r"(a[1]), "r"(a[2]), "r"(a[3]), "r"(b0), "r"(b1));
}

__device__ __forceinline__ void split1h(float x, __half& h, __half& l) {
    h = __float2half_rn(x);
    l = __float2half_rn(x - __half2float(h));
}

// ============================================================
// merged split: x (4 quarters, fp16 unsplit) + 4 weights (hi/lo)
// ============================================================
__global__ void split_all(const float* __restrict__ x,
                          const float* __restrict__ Wq, const float* __restrict__ Wk,
                          const float* __restrict__ Wv, const float* __restrict__ Wo,
                          __half* __restrict__ ah,
                          __half* __restrict__ wh, __half* __restrict__ wl)
{
    const int yy = blockIdx.y;
    const size_t i = (size_t)blockIdx.x * blockDim.x + threadIdx.x;
    const size_t e = i * 4;
    if (yy < 4) {
        const float* src = x + (size_t)yy * (MT*DM/4) + e;
        __half* hp = ah + (size_t)yy * (MT*DM/4) + e;
        float4 xx = *(const float4*)src;
        __half2* h2 = (__half2*)hp;
        h2[0] = __half2(__float2half_rn(xx.x), __float2half_rn(xx.y));
        h2[1] = __half2(__float2half_rn(xx.z), __float2half_rn(xx.w));
    } else {
        const float* ws[4] = {Wq, Wk, Wv, Wo};
        const float* src = ws[yy-4] + e;
        __half* hp = wh + (size_t)(yy-4) * DM*DM + e;
        __half* lp = wl + (size_t)(yy-4) * DM*DM + e;
        float4 xx = *(const float4*)src;
        __half h0, h1, h2v, h3, l0, l1, l2, l3;
        split1h(xx.x, h0, l0); split1h(xx.y, h1, l1);
        split1h(xx.z, h2v, l2); split1h(xx.w, h3, l3);
        ((__half2*)hp)[0] = __half2(h0, h1); ((__half2*)hp)[1] = __half2(h2v, h3);
        ((__half2*)lp)[0] = __half2(l0, l1); ((__half2*)lp)[1] = __half2(l2, l3);
    }
}

// ============================================================
// HMMA fp16 GEMM, 2-product compensated (A fp16, B = Bh+Bl)
// ============================================================
#define GSM_BYTES (2*3*128*40*2)   // 61440

__global__ __launch_bounds__(256, 2)
void gemm_mma(const __half* __restrict__ Ah,
              const __half* __restrict__ Wh, const __half* __restrict__ Wl,
              float* __restrict__ C0, float* __restrict__ C1, float* __restrict__ C2,
              int M, int N, int K, int wbase)
{
    extern __shared__ __half smh[];
    const uint32_t sbase = smem_u32(smh);
    const int tid = threadIdx.x;
    const int lane = tid & 31;
    const int w = tid >> 5;
    const int wr = w >> 2;
    const int wc = w & 3;
    const int m0 = blockIdx.y * 128;
    const int n0 = blockIdx.x * 128;
    const int z = blockIdx.z;

    float* C = (z == 0) ? C0 : (z == 1) ? C1 : C2;
    const size_t woff = (size_t)(wbase + z) * DM * DM;
    const __half* Bh = Wh + woff;
    const __half* Bl = Wl + woff;

    const int lrow = tid >> 2;
    const int lc16 = tid & 3;

    const __half* gsrc[3] = {Ah, Bh, Bl};

    float acc[4][4][4];
    #pragma unroll
    for (int m = 0; m < 4; m++)
        #pragma unroll
        for (int n = 0; n < 4; n++)
            #pragma unroll
            for (int e = 0; e < 4; e++) acc[m][n][e] = 0.f;

    const int NCH = K >> 5;

    auto load_stage = [&](int s, int k0) {
        uint32_t sb = sbase + (uint32_t)s * 15360u * 2u;
        #pragma unroll
        for (int arr = 0; arr < 3; arr++) {
            const __half* g = gsrc[arr];
            int base_row = (arr == 0) ? m0 : n0;
            #pragma unroll
            for (int half = 0; half < 2; half++) {
                int row = lrow + half * 64;
                uint32_t so = sb + (uint32_t)(arr * 5120 + row * 40 + lc16 * 8) * 2u;
                const __half* gp = g + (size_t)(base_row + row) * K + k0 + lc16 * 8;
                CP16(so, gp);
            }
        }
    };

    load_stage(0, 0);
    asm volatile("cp.async.commit_group;" ::: "memory");

    for (int c = 0; c < NCH; ++c) {
        const int s = c & 1;
        if (c + 1 < NCH) {
            load_stage(s ^ 1, (c + 1) << 5);
            asm volatile("cp.async.commit_group;" ::: "memory");
            asm volatile("cp.async.wait_group 1;" ::: "memory");
        } else {
            asm volatile("cp.async.wait_group 0;" ::: "memory");
        }
        __syncthreads();

        const uint32_t sb = sbase + (uint32_t)s * 15360u * 2u;
        const uint32_t sA  = sb;
        const uint32_t sB  = sb + 5120u * 2u;
        const uint32_t sBl = sb + 10240u * 2u;

        #pragma unroll
        for (int kk = 0; kk < 2; ++kk) {
            const int kb = kk * 16;
            uint32_t ah4[4][4];
            const uint32_t arow = (uint32_t)(wr * 64 + (lane & 15));
            const uint32_t acol = (uint32_t)(kb + (lane >> 4) * 8);
            #pragma unroll
            for (int m = 0; m < 4; m++) {
                uint32_t off = ((arow + m * 16) * 40u + acol) * 2u;
                ldmx4(ah4[m], sA + off);
            }
            uint32_t bh4[2][4], bl4[2][4];
            const uint32_t brow = (uint32_t)(wc * 32 + (lane & 7) + ((lane >> 4) << 3));
            const uint32_t bcol = (uint32_t)(kb + ((lane >> 3) & 1) * 8);
            #pragma unroll
            for (int p = 0; p < 2; p++) {
                uint32_t off = ((brow + p * 16) * 40u + bcol) * 2u;
                ldmx4(bh4[p], sB  + off);
                ldmx4(bl4[p], sBl + off);
            }
            #pragma unroll
            for (int m = 0; m < 4; m++) {
                #pragma unroll
                for (int n = 0; n < 4; n++) {
                    uint32_t b0 = bh4[n >> 1][(n & 1) * 2];
                    uint32_t b1 = bh4[n >> 1][(n & 1) * 2 + 1];
                    uint32_t c0 = bl4[n >> 1][(n & 1) * 2];
                    uint32_t c1 = bl4[n >> 1][(n & 1) * 2 + 1];
                    mma16816h(acc[m][n], ah4[m], b0, b1);
                    mma16816h(acc[m][n], ah4[m], c0, c1);
                }
            }
        }
        __syncthreads();
    }

    const int r0 = m0 + wr * 64 + (lane >> 2);
    const int cc = n0 + wc * 32 + (lane & 3) * 2;
    #pragma unroll
    for (int m = 0; m < 4; m++) {
        #pragma unroll
        for (int n = 0; n < 4; n++) {
            float* p0 = C + (size_t)(r0 + m * 16) * N + cc + n * 8;
            float* p1 = C + (size_t)(r0 + m * 16 + 8) * N + cc + n * 8;
            *(float2*)p0 = make_float2(acc[m][n][0], acc[m][n][1]);
            *(float2*)p1 = make_float2(acc[m][n][2], acc[m][n][3]);
        }
    }
}

// ============================================================
// chunk_state: grid (NC, BH); P[bh][ch] = sum_j gamma^(CH-j) k_j v_j^T
// CH=64 -> one block per chunk, 64 rows
// ============================================================
__global__ __launch_bounds__(256)
void chunk_state(const float* __restrict__ kmat, const float* __restrict__ vmat,
                 float* __restrict__ P)
{
    __shared__ float Ks[64][68];
    __shared__ float Vs[64][68];
    const int ch = blockIdx.x;
    const int bh = blockIdx.y;
    const int b = bh >> 4, h = bh & 15;
    const float lg = log2f(1.f - exp2f(-5.f - (float)h));
    const int tid = threadIdx.x;
    const int j0 = ch * CH;

    const float* kbase = kmat + ((size_t)(b*TT + j0))*DM + h*DH;
    const float* vbase = vmat + ((size_t)(b*TT + j0))*DM + h*DH;
    for (int s = tid; s < 64*16; s += 256) {
        int row = s >> 4, c4 = (s & 15) << 2;
        float sc = exp2f(lg * (float)(CH - row));
        float4 kk = *(const float4*)(kbase + (size_t)row*DM + c4);
        Ks[row][c4+0] = kk.x*sc; Ks[row][c4+1] = kk.y*sc;
        Ks[row][c4+2] = kk.z*sc; Ks[row][c4+3] = kk.w*sc;
        float4 vv = *(const float4*)(vbase + (size_t)row*DM + c4);
        *(float4*)&Vs[row][c4] = vv;
    }
    __syncthreads();

    const int tr = tid >> 4, tc = tid & 15;
    float acc[4][4];
    #pragma unroll
    for (int i = 0; i < 4; i++)
        #pragma unroll
        for (int j = 0; j < 4; j++) acc[i][j] = 0.f;

    #pragma unroll 4
    for (int j = 0; j < 64; j++) {
        float ar[4], br[4];
        *(float4*)&ar[0] = *(const float4*)&Ks[j][tr*4];
        *(float4*)&br[0] = *(const float4*)&Vs[j][tc*4];
        #pragma unroll
        for (int i = 0; i < 4; i++)
            #pragma unroll
            for (int jj = 0; jj < 4; jj++)
                acc[i][jj] += ar[i] * br[jj];
    }

    float* pbase = P + ((size_t)(bh*NC + ch))*DH*DH;
    #pragma unroll
    for (int i = 0; i < 4; i++)
        *(float4*)(pbase + (tr*4 + i)*DH + tc*4) =
            make_float4(acc[i][0], acc[i][1], acc[i][2], acc[i][3]);
}

// ============================================================
// state_scan: parallel over elements; NC=32 serial steps, gamma^64 decay
// ============================================================
__global__ __launch_bounds__(256)
void state_scan(const float* __restrict__ P, float* __restrict__ S)
{
    const int bh = blockIdx.y;
    const int e = blockIdx.x * 256 + threadIdx.x;   // 0..4095
    const int h = bh & 15;
    const float lg = log2f(1.f - exp2f(-5.f - (float)h));
    const float gC = exp2f(lg * (float)CH);

    float s = 0.f;
    #pragma unroll
    for (int n = 0; n < NC; n++) {
        const size_t base = ((size_t)(bh*NC + n))*DH*DH;
        S[base + e] = s * 0.125f;
        s = gC * s + P[base + e];
    }
}

// ============================================================
// retention64: per (chunk, bh) block: 64 q-rows x 64 cols
// y = Qs @ State + mask(Qs@Ks^T)/8 @ V ; 4x4 microtile, 256 thr
// smem: QT 64x68 + KT 64x68 + Vs 64x68 + Ss 64x68 = 69.6KB -> 3 CTAs/SM
// ============================================================
#define RET_SMEM_FLOATS (4*64*68)

__global__ __launch_bounds__(256)
void retention64(const float* __restrict__ q, const float* __restrict__ kmat,
                 const float* __restrict__ vmat, const float* __restrict__ Sg,
                 float* __restrict__ y)
{
    extern __shared__ float smf[];
    float (*QT)[68] = (float (*)[68])smf;                 // [c][i] transposed Q
    float (*KT)[68] = (float (*)[68])(smf + 64*68);       // state [a][c], then K [c][j]
    float (*Vs)[68] = (float (*)[68])(smf + 2*64*68);     // V [j][c]
    float (*Ss)[68] = (float (*)[68])(smf + 3*64*68);     // S [i][j]

    const int it = blockIdx.x;          // chunk 0..31
    const int bh = blockIdx.y;
    const int b = bh >> 4, h = bh & 15;
    const int i0 = it * CH;
    const float lg = log2f(1.f - exp2f(-5.f - (float)h));
    const int tid = threadIdx.x;
    const int tr = tid >> 4;            // 0..15 -> 4 rows
    const int tc = tid & 15;            // 0..15 -> 4 cols

    // load Q tile [64x64] transposed + scaled gamma^row ; state into KT [a][c]
    const float* qbase = q + ((size_t)(b*TT + i0))*DM + h*DH;
    const float* sbase = Sg + ((size_t)(bh*NC + it))*DH*DH;
    for (int s = tid; s < 64*16; s += 256) {
        int row = s >> 4, c4 = (s & 15) << 2;
        float4 a = *(const float4*)(qbase + (size_t)row*DM + c4);
        float sc = exp2f(lg * (float)row);
        QT[c4+0][row] = a.x*sc; QT[c4+1][row] = a.y*sc;
        QT[c4+2][row] = a.z*sc; QT[c4+3][row] = a.w*sc;
        *(float4*)&KT[row][c4] = *(const float4*)(sbase + row*DH + c4);
    }
    __syncthreads();

    float accy[4][4];
    #pragma unroll
    for (int i = 0; i < 4; i++)
        #pragma unroll
        for (int j = 0; j < 4; j++) accy[i][j] = 0.f;

    // inter-chunk: accy[i][c] += sum_a QT[a][i] * State[a][c]
    #pragma unroll 8
    for (int a = 0; a < DH; a++) {
        float ar[4], br[4];
        *(float4*)&ar[0] = *(const float4*)&QT[a][tr*4];
        *(float4*)&br[0] = *(const float4*)&KT[a][tc*4];
        #pragma unroll
        for (int i = 0; i < 4; i++)
            #pragma unroll
            for (int j = 0; j < 4; j++)
                accy[i][j] += ar[i] * br[j];
    }

    // intra-chunk (single masked diagonal tile)
    __syncthreads();   // done reading state from KT
    {
        const float* kbase = kmat + ((size_t)(b*TT + i0))*DM + h*DH;
        const float* vbase = vmat + ((size_t)(b*TT + i0))*DM + h*DH;
        for (int s = tid; s < 64*16; s += 256) {
            int row = s >> 4, c4 = (s & 15) << 2;
            float sc = exp2f(-lg * (float)row);   // gamma^-j
            float4 kk = *(const float4*)(kbase + (size_t)row*DM + c4);
            KT[c4+0][row] = kk.x*sc; KT[c4+1][row] = kk.y*sc;
            KT[c4+2][row] = kk.z*sc; KT[c4+3][row] = kk.w*sc;
            float4 vv = *(const float4*)(vbase + (size_t)row*DM + c4);
            *(float4*)&Vs[row][c4] = vv;
        }
    }
    __syncthreads();

    float acc1[4][4];
    #pragma unroll
    for (int i = 0; i < 4; i++)
        #pragma unroll
        for (int j = 0; j < 4; j++) acc1[i][j] = 0.f;
    #pragma unroll 8
    for (int c = 0; c < DH; c++) {
        float ar[4], br[4];
        *(float4*)&ar[0] = *(const float4*)&QT[c][tr*4];
        *(float4*)&br[0] = *(const float4*)&KT[c][tc*4];
        #pragma unroll
        for (int i = 0; i < 4; i++)
            #pragma unroll
            for (int j = 0; j < 4; j++)
                acc1[i][j] += ar[i] * br[j];
    }

    #pragma unroll
    for (int i = 0; i < 4; i++) {
        const int ir = tr*4 + i;
        float o0 = acc1[i][0]*0.125f, o1 = acc1[i][1]*0.125f;
        float o2 = acc1[i][2]*0.125f, o3 = acc1[i][3]*0.125f;
        int d0 = ir - (tc*4);
        if (d0     < 0) o0 = 0.f;
        if (d0 - 1 < 0) o1 = 0.f;
        if (d0 - 2 < 0) o2 = 0.f;
        if (d0 - 3 < 0) o3 = 0.f;
        *(float4*)&Ss[ir][tc*4] = make_float4(o0, o1, o2, o3);
    }
    __syncthreads();

    // y += S @ V
    #pragma unroll 8
    for (int jr = 0; jr < 64; jr++) {
        float br[4];
        *(float4*)&br[0] = *(const float4*)&Vs[jr][tc*4];
        #pragma unroll
        for (int i = 0; i < 4; i++) {
            float sv = Ss[tr*4+i][jr];
            accy[i][0] += sv * br[0];
            accy[i][1] += sv * br[1];
            accy[i][2] += sv * br[2];
            accy[i][3] += sv * br[3];
        }
    }

    float* ybase = y + ((size_t)(b*TT + i0))*DM + h*DH;
    #pragma unroll
    for (int i = 0; i < 4; i++) {
        *(float4*)(ybase + (size_t)(tr*4 + i)*DM + tc*4) =
            make_float4(accy[i][0], accy[i][1], accy[i][2], accy[i][3]);
    }
}

// ============================================================
// GroupNorm: phase-1 partial reduce + fused (stats + apply + fp16 convert)
// ============================================================
__global__ void gn_reduce1(const float* __restrict__ y, float* __restrict__ part)
{
    const int bh = blockIdx.x;
    const int slab = blockIdx.y;
    const int b = bh >> 4, h = bh & 15;
    const float* base = y + (size_t)b*TT*DM + (size_t)slab*(TT/8)*DM + h*DH;
    float s = 0.f, s2 = 0.f;
    for (int sl = threadIdx.x; sl < (TT/8)*16; sl += blockDim.x) {
        int t = sl >> 4, c4 = (sl & 15) << 2;
        float4 vv = *(const float4*)(base + (size_t)t*DM + c4);
        s  += vv.x + vv.y + vv.z + vv.w;
        s2 += vv.x*vv.x + vv.y*vv.y + vv.z*vv.z + vv.w*vv.w;
    }
    #pragma unroll
    for (int o = 16; o > 0; o >>= 1) {
        s  += __shfl_down_sync(0xffffffffu, s,  o);
        s2 += __shfl_down_sync(0xffffffffu, s2, o);
    }
    __shared__ float rs[32], rs2[32];
    const int wid = threadIdx.x >> 5, lid = threadIdx.x & 31;
    if (lid == 0) { rs[wid] = s; rs2[wid] = s2; }
    __syncthreads();
    if (wid == 0) {
        const int nw = blockDim.x >> 5;
        s  = (lid < nw) ? rs[lid]  : 0.f;
        s2 = (lid < nw) ? rs2[lid] : 0.f;
        #pragma unroll
        for (int o = 16; o > 0; o >>= 1) {
            s  += __shfl_down_sync(0xffffffffu, s,  o);
            s2 += __shfl_down_sync(0xffffffffu, s2, o);
        }
        if (lid == 0) {
            part[(bh*8 + slab)*2]   = s;
            part[(bh*8 + slab)*2+1] = s2;
        }
    }
}

__global__ void gn_apply_split(const float* __restrict__ y, const float* __restrict__ part,
                               const float* __restrict__ gw, const float* __restrict__ gb,
                               __half* __restrict__ hi)
{
    size_t e = ((size_t)blockIdx.x * blockDim.x + threadIdx.x) * 4;
    int col = (int)(e % DM);
    size_t row = e / DM;
    int b = (int)(row / TT);
    int g = b * 16 + (col >> 6);
    float s = 0.f, s2 = 0.f;
    #pragma unroll
    for (int i = 0; i < 8; i++) {
        s  += part[(g*8 + i)*2];
        s2 += part[(g*8 + i)*2+1];
    }
    const float invN = 1.f / (float)(TT * DH);
    float mean = s * invN;
    float rstd = rsqrtf(s2 * invN - mean * mean + 1e-5f);
    float4 vv = *(const float4*)(y + e);
    float4 w4 = *(const float4*)(gw + col);
    float4 b4 = *(const float4*)(gb + col);
    float o0 = (vv.x - mean) * rstd * w4.x + b4.x;
    float o1 = (vv.y - mean) * rstd * w4.y + b4.y;
    float o2 = (vv.z - mean) * rstd * w4.z + b4.z;
    float o3 = (vv.w - mean) * rstd * w4.w + b4.w;
    __half2* hp = (__half2*)(hi + e);
    hp[0] = __half2(__float2half_rn(o0), __float2half_rn(o1));
    hp[1] = __half2(__float2half_rn(o2), __float2half_rn(o3));
}

// ============================================================
extern "C" void kernel_launch(void* const* d_in, const int* in_sizes, int n_in,
                              void* d_out, int out_size)
{
    const float* x  = (const float*)d_in[0];
    const float* Wq = (const float*)d_in[1];
    const float* Wk = (const float*)d_in[2];
    const float* Wv = (const float*)d_in[3];
    const float* Wo = (const float*)d_in[4];
    const float* gw = (const float*)d_in[5];
    const float* gb = (const float*)d_in[6];
    float* out = (float*)d_out;

    float *q, *k, *v, *y, *pt, *P, *S;
    __half *ah, *wh, *wl;
    cudaGetSymbolAddress((void**)&q,  g_q);
    cudaGetSymbolAddress((void**)&k,  g_k);
    cudaGetSymbolAddress((void**)&v,  g_v);
    cudaGetSymbolAddress((void**)&y,  g_y);
    cudaGetSymbolAddress((void**)&pt, g_part);
    cudaGetSymbolAddress((void**)&P,  g_P);
    cudaGetSymbolAddress((void**)&S,  g_S);
    cudaGetSymbolAddress((void**)&ah, g_ah);
    cudaGetSymbolAddress((void**)&wh, g_wh);
    cudaGetSymbolAddress((void**)&wl, g_wl);

    const int ret_smem = RET_SMEM_FLOATS * (int)sizeof(float);
    cudaFuncSetAttribute(retention64, cudaFuncAttributeMaxDynamicSharedMemorySize, ret_smem);
    cudaFuncSetAttribute(gemm_mma, cudaFuncAttributeMaxDynamicSharedMemorySize, GSM_BYTES);

    // one merged split launch (x + 4 weights)
    split_all<<<dim3(1024, 8), 256>>>(x, Wq, Wk, Wv, Wo, ah, wh, wl);

    // batched QKV GEMM
    dim3 gq(DM/128, MT/128, 3);
    gemm_mma<<<gq, 256, GSM_BYTES>>>(ah, wh, wl, q, k, v, MT, DM, DM, 0);

    chunk_state<<<dim3(NC, BB*NH), 256>>>(k, v, P);
    state_scan<<<dim3(16, BB*NH), 256>>>(P, S);
    retention64<<<dim3(NC, BB*NH), 256, ret_smem>>>(q, k, v, S, y);

    gn_reduce1<<<dim3(BB*NH, 8), 512>>>(y, pt);
    gn_apply_split<<<(MT*DM)/(4*256), 256>>>(y, pt, gw, gb, ah);

    // output GEMM (weight index 3)
    dim3 go(DM/128, MT/128, 1);
    gemm_mma<<<go, 256, GSM_BYTES>>>(ah, wh, wl, out, out, out, MT, DM, DM, 3);
}